// round 15
// baseline (speedup 1.0000x reference)
#include <cuda_runtime.h>
#include <cuda_bf16.h>
#include <math.h>
#include <stdint.h>

#define BB 16
#define CC 256
#define LL 2048
#define EE 512
#define NN 64
#define HH 512
#define H2 1024

// weight offsets in bf16 scratch (cumulative)
#define W1_OFF 0
#define W2_OFF 131072
#define W3_OFF 655360
#define W4_OFF 1179648
#define WTOT   1310720
#define XTOT   (BB * CC * LL)

// ---------------- scratch ----------------
__device__ float          g_e[BB * HH];
__device__ float          g_u[BB * HH * LL];
__device__ float          g_t[(size_t)BB * H2 * LL];
__device__ __nv_bfloat16  g_bh[BB * HH * LL];
__device__ __nv_bfloat16  g_bl[BB * HH * LL];
__device__ __nv_bfloat16  g_wh[WTOT];
__device__ __nv_bfloat16  g_wl[WTOT];

// ---------------- math helpers ----------------
__device__ __forceinline__ float sigf(float x) {
    return __fdividef(1.f, 1.f + __expf(-x));
}
__device__ __forceinline__ float tanh_fast(float x) {
    return fmaf(2.f, __fdividef(1.f, 1.f + __expf(-2.f * x)), -1.f);
}
__device__ __forceinline__ float geluf(float x) {
    float t = x * fmaf(0.044715f, x * x, 1.f);
    return x * sigf(1.5957691216057308f * t);
}
__device__ __forceinline__ uint32_t pack_bf16(__nv_bfloat16 a, __nv_bfloat16 b) {
    __nv_bfloat162 v(a, b);
    return *(uint32_t*)&v;
}
__device__ __forceinline__ void split2(float v0, float v1, uint32_t& hi, uint32_t& lo) {
    __nv_bfloat16 h0 = __float2bfloat16(v0);
    __nv_bfloat16 h1 = __float2bfloat16(v1);
    __nv_bfloat16 q0 = __float2bfloat16(v0 - __bfloat162float(h0));
    __nv_bfloat16 q1 = __float2bfloat16(v1 - __bfloat162float(h1));
    hi = pack_bf16(h0, h1);
    lo = pack_bf16(q0, q1);
}

// ---------------- packed f32x2 ----------------
__device__ __forceinline__ uint64_t packf2(float lo, float hi) {
    uint64_t r;
    asm("mov.b64 %0, {%1,%2};" : "=l"(r) : "f"(lo), "f"(hi));
    return r;
}
__device__ __forceinline__ void unpackf2(uint64_t v, float& lo, float& hi) {
    asm("mov.b64 {%0,%1}, %2;" : "=f"(lo), "=f"(hi) : "l"(v));
}
__device__ __forceinline__ uint64_t fma2(uint64_t a, uint64_t b, uint64_t c) {
    uint64_t d;
    asm("fma.rn.f32x2 %0, %1, %2, %3;" : "=l"(d) : "l"(a), "l"(b), "l"(c));
    return d;
}
__device__ __forceinline__ uint64_t mul2(uint64_t a, uint64_t b) {
    uint64_t d;
    asm("mul.rn.f32x2 %0, %1, %2;" : "=l"(d) : "l"(a), "l"(b));
    return d;
}

// ---------------- fused conversion: all weights + x -> bf16 hi/lo ----------------
__global__ void k_conv(const float* __restrict__ w0, const float* __restrict__ w1,
                       const float* __restrict__ w2, const float* __restrict__ w3,
                       const float* __restrict__ x,
                       __nv_bfloat16* __restrict__ wh, __nv_bfloat16* __restrict__ wl,
                       __nv_bfloat16* __restrict__ xh, __nv_bfloat16* __restrict__ xl) {
    int i4 = blockIdx.x * 256 + threadIdx.x;
    float4 v;
    __nv_bfloat16 *oh, *ol;
    size_t off;
    if (i4 < WTOT / 4) {
        int i = i4 * 4;
        const float* src;
        if (i < W2_OFF) src = w0 + i;
        else if (i < W3_OFF) src = w1 + (i - W2_OFF);
        else if (i < W4_OFF) src = w2 + (i - W3_OFF);
        else src = w3 + (i - W4_OFF);
        v = *(const float4*)src;
        oh = wh; ol = wl; off = (size_t)i;
    } else {
        size_t i = (size_t)(i4 - WTOT / 4) * 4;
        v = *(const float4*)(x + i);
        oh = xh; ol = xl; off = i;
    }
    uint2 h, l;
    split2(v.x, v.y, h.x, l.x);
    split2(v.z, v.w, h.y, l.y);
    *(uint2*)(oh + off) = h;
    *(uint2*)(ol + off) = l;
}

// ---------------- fused diffusion proj + input bias ----------------
__global__ void k_debias(const float* __restrict__ demb, const float* __restrict__ dpW,
                         const float* __restrict__ dpb, const float* __restrict__ inW,
                         const float* __restrict__ inb, float* __restrict__ e) {
    int b = blockIdx.x;
    int t = threadIdx.x;
    __shared__ float se[EE];
    __shared__ float sd[CC];
    for (int i = t; i < EE; i += 256) se[i] = demb[b * EE + i];
    __syncthreads();
    {
        float acc = 0.f;
#pragma unroll 8
        for (int k = 0; k < EE; k++) acc = fmaf(dpW[(size_t)t * EE + k], se[k], acc);
        sd[t] = acc + dpb[t];
    }
    __syncthreads();
    for (int o = t; o < HH; o += 256) {
        float acc = 0.f;
#pragma unroll 8
        for (int k = 0; k < CC; k++) acc = fmaf(inW[(size_t)o * CC + k], sd[k], acc);
        e[b * HH + o] = acc + inb[o];
    }
}

// ---------------- diagonal SSM recurrence (prec fused) + D-skip + GELU -> bf16 hi/lo ----------------
// 2 sequences per warp (16 lanes each); 4 complex states/lane = 2 packed groups;
// prefetch ring depth 4; batched 4-chain shfl reductions (4 levels).
__global__ void k_ssm(const float* __restrict__ in, __nv_bfloat16* __restrict__ outh,
                      __nv_bfloat16* __restrict__ outl,
                      const float* __restrict__ log_dt, const float* __restrict__ Are,
                      const float* __restrict__ Aim, const float* __restrict__ Cre,
                      const float* __restrict__ Cim, const float* __restrict__ Dv) {
    int warpId = (blockIdx.x * blockDim.x + threadIdx.x) >> 5;
    int lane = threadIdx.x & 31;
    int sub = lane >> 4;                 // 0..1 sequence in warp
    int ll = lane & 15;                  // lane within 16-lane group
    int seq = warpId * 2 + sub;
    int b = seq >> 9, h = seq & (HH - 1);

    // fused precompute: 4 states per lane -> 2 packed groups
    float dt = expf(log_dt[h]);
    uint64_t zr[2], zi[2], nzi[2], cr[2], nci[2];
#pragma unroll
    for (int g = 0; g < 2; g++) {
        float zrv[2], ziv[2], ctr[2], cti[2];
#pragma unroll
        for (int q = 0; q < 2; q++) {
            int idx = h * NN + ll * 4 + 2 * g + q;
            float A_r = Are[idx], A_i = Aim[idx];
            float er = expf(A_r * dt);
            float s, c0;
            sincosf(A_i * dt, &s, &c0);
            float zrr = er * c0, zii = er * s;
            float wr = zrr - 1.f, wi = zii;
            float inv = 1.f / (A_r * A_r + A_i * A_i);
            float qr = (wr * A_r + wi * A_i) * inv;
            float qi = (wi * A_r - wr * A_i) * inv;
            float crv = Cre[idx], civ = Cim[idx];
            ctr[q] = 2.f * (crv * qr - civ * qi);
            cti[q] = 2.f * (crv * qi + civ * qr);
            zrv[q] = zrr;
            ziv[q] = zii;
        }
        zr[g] = packf2(zrv[0], zrv[1]);
        zi[g] = packf2(ziv[0], ziv[1]);
        nzi[g] = packf2(-ziv[0], -ziv[1]);
        cr[g] = packf2(ctr[0], ctr[1]);
        nci[g] = packf2(-cti[0], -cti[1]);
    }
    float Dh = Dv[h];

    const float4* ip = (const float4*)(in + (size_t)(b * HH + h) * LL);
    __nv_bfloat16* oph = outh + (size_t)(b * HH + h) * LL;
    __nv_bfloat16* opl = outl + (size_t)(b * HH + h) * LL;

    uint64_t sr[2], si[2];
#pragma unroll
    for (int g = 0; g < 2; g++) { sr[g] = packf2(0.f, 0.f); si[g] = sr[g]; }

    float4 buf[4];
#pragma unroll
    for (int i = 0; i < 4; i++) buf[i] = __ldg(ip + i);

#pragma unroll 4
    for (int l4 = 0; l4 < LL / 4; l4++) {
        float4 u4 = buf[l4 & 3];
        if (l4 + 4 < LL / 4) buf[l4 & 3] = __ldg(ip + l4 + 4);
        float pj[4];
#pragma unroll
        for (int j = 0; j < 4; j++) {
            float u = (j == 0) ? u4.x : (j == 1) ? u4.y : (j == 2) ? u4.z : u4.w;
            uint64_t uu = packf2(u, u);
#pragma unroll
            for (int g = 0; g < 2; g++) {
                uint64_t tg = fma2(nzi[g], si[g], uu);
                uint64_t mg = mul2(zi[g], sr[g]);
                sr[g] = fma2(zr[g], sr[g], tg);
                si[g] = fma2(zr[g], si[g], mg);
            }
            uint64_t acc = mul2(nci[0], si[0]);
            acc = fma2(cr[0], sr[0], acc);
            acc = fma2(nci[1], si[1], acc);
            acc = fma2(cr[1], sr[1], acc);
            float pl, ph;
            unpackf2(acc, pl, ph);
            pj[j] = pl + ph;
        }
        // batched butterfly across 16 lanes: 4 independent chains per level
#pragma unroll
        for (int off = 8; off; off >>= 1) {
            pj[0] += __shfl_xor_sync(0xffffffffu, pj[0], off);
            pj[1] += __shfl_xor_sync(0xffffffffu, pj[1], off);
            pj[2] += __shfl_xor_sync(0xffffffffu, pj[2], off);
            pj[3] += __shfl_xor_sync(0xffffffffu, pj[3], off);
        }
        float g0 = geluf(fmaf(Dh, u4.x, pj[0]));
        float g1 = geluf(fmaf(Dh, u4.y, pj[1]));
        float g2 = geluf(fmaf(Dh, u4.z, pj[2]));
        float g3 = geluf(fmaf(Dh, u4.w, pj[3]));
        uint2 hv, lv;
        split2(g0, g1, hv.x, lv.x);
        split2(g2, g3, hv.y, lv.y);
        if (ll == 0) {
            *(uint2*)(oph + l4 * 4) = hv;
            *(uint2*)(opl + l4 * 4) = lv;
        }
    }
}

// ======================================================================
// pure-bf16 split GEMM, block 64(O)x128(L), K-chunk 32, 3 CTAs/SM
// ======================================================================
#define SA2 40
#define SB_STR 136
#define A_ELE (64 * SA2)
#define B_ELE (32 * SB_STR)
#define GEMM_SMEM ((4 * A_ELE + 4 * B_ELE) * 2)   /* 55296 bytes */

__device__ __forceinline__ void cp16(uint32_t dst, const void* src) {
    asm volatile("cp.async.ca.shared.global [%0], [%1], 16;\n" :: "r"(dst), "l"(src));
}
__device__ __forceinline__ void ldsm_x4(uint32_t& r0, uint32_t& r1, uint32_t& r2,
                                        uint32_t& r3, uint32_t addr) {
    asm volatile("ldmatrix.sync.aligned.m8n8.x4.shared.b16 {%0,%1,%2,%3}, [%4];"
                 : "=r"(r0), "=r"(r1), "=r"(r2), "=r"(r3) : "r"(addr));
}
__device__ __forceinline__ void ldsm_x4t(uint32_t& r0, uint32_t& r1, uint32_t& r2,
                                         uint32_t& r3, uint32_t addr) {
    asm volatile("ldmatrix.sync.aligned.m8n8.x4.trans.shared.b16 {%0,%1,%2,%3}, [%4];"
                 : "=r"(r0), "=r"(r1), "=r"(r2), "=r"(r3) : "r"(addr));
}
__device__ __forceinline__ void mma16816(float* c, const uint32_t* a, const uint32_t* b) {
    asm volatile("mma.sync.aligned.m16n8k16.row.col.f32.bf16.bf16.f32 "
                 "{%0,%1,%2,%3}, {%4,%5,%6,%7}, {%8,%9}, {%0,%1,%2,%3};"
                 : "+f"(c[0]), "+f"(c[1]), "+f"(c[2]), "+f"(c[3])
                 : "r"(a[0]), "r"(a[1]), "r"(a[2]), "r"(a[3]), "r"(b[0]), "r"(b[1]));
}

__global__ __launch_bounds__(256, 3)
void k_gemm_bf(const __nv_bfloat16* __restrict__ Ah_, const __nv_bfloat16* __restrict__ Al_,
               const __nv_bfloat16* __restrict__ Bh_, const __nv_bfloat16* __restrict__ Bl_,
               const float* __restrict__ bias, int bias_per_batch,
               float* __restrict__ Y, int O, int K,
               const float* __restrict__ xres, int final_mode) {
    extern __shared__ __align__(16) __nv_bfloat16 dsm[];
    __nv_bfloat16* sAh = dsm;
    __nv_bfloat16* sAl = sAh + 2 * A_ELE;
    __nv_bfloat16* sBh = sAl + 2 * A_ELE;
    __nv_bfloat16* sBl = sBh + 2 * B_ELE;

    int t = threadIdx.x, lane = t & 31, warp = t >> 5;
    int wo = warp >> 2, wl = warp & 3;
    int o0 = blockIdx.y * 64, l0 = blockIdx.x * 128, b = blockIdx.z;
    const __nv_bfloat16* BhB = Bh_ + (size_t)b * K * LL;
    const __nv_bfloat16* BlB = Bl_ + (size_t)b * K * LL;
    int nk = K / 32;

    float acc[2][4][4];
#pragma unroll
    for (int i = 0; i < 2; i++)
#pragma unroll
        for (int j = 0; j < 4; j++)
#pragma unroll
            for (int q = 0; q < 4; q++) acc[i][j][q] = 0.f;

#define STAGE(buf, kb)                                                                     \
    do {                                                                                   \
        {                                                                                  \
            int arow = t >> 2, acs = (t & 3) * 8;                                          \
            cp16((uint32_t)__cvta_generic_to_shared(                                       \
                     sAh + (buf) * A_ELE + arow * SA2 + acs),                              \
                 Ah_ + (size_t)(o0 + arow) * K + (kb) + acs);                              \
            cp16((uint32_t)__cvta_generic_to_shared(                                       \
                     sAl + (buf) * A_ELE + arow * SA2 + acs),                              \
                 Al_ + (size_t)(o0 + arow) * K + (kb) + acs);                              \
        }                                                                                  \
        _Pragma("unroll")                                                                  \
        for (int q = 0; q < 2; q++) {                                                      \
            int idx = q * 256 + t;                                                         \
            int brow = idx >> 4, bcs = (idx & 15) * 8;                                     \
            cp16((uint32_t)__cvta_generic_to_shared(                                       \
                     sBh + (buf) * B_ELE + brow * SB_STR + bcs),                           \
                 BhB + (size_t)((kb) + brow) * LL + l0 + bcs);                             \
            cp16((uint32_t)__cvta_generic_to_shared(                                       \
                     sBl + (buf) * B_ELE + brow * SB_STR + bcs),                           \
                 BlB + (size_t)((kb) + brow) * LL + l0 + bcs);                             \
        }                                                                                  \
        asm volatile("cp.async.commit_group;\n");                                         \
    } while (0)

    STAGE(0, 0);
    asm volatile("cp.async.wait_group 0;\n");
    __syncthreads();

    int aRowL = wo * 32 + (lane & 15);
    int aColL = (lane >> 4) * 8;
    int bRowL = lane & 15;
    int bColL = wl * 32 + (lane >> 4) * 8;

    for (int kc = 0; kc < nk; kc++) {
        int cur = kc & 1;
        bool more = (kc + 1) < nk;
        if (more) STAGE(cur ^ 1, (kc + 1) * 32);

        uint32_t aHb = (uint32_t)__cvta_generic_to_shared(sAh + cur * A_ELE);
        uint32_t aLb = (uint32_t)__cvta_generic_to_shared(sAl + cur * A_ELE);
        uint32_t bHb = (uint32_t)__cvta_generic_to_shared(sBh + cur * B_ELE);
        uint32_t bLb = (uint32_t)__cvta_generic_to_shared(sBl + cur * B_ELE);

#pragma unroll
        for (int kh = 0; kh < 2; kh++) {
            uint32_t aOff0 = (uint32_t)((aRowL * SA2 + aColL + kh * 16) * 2);
            uint32_t aH[2][4], aL[2][4], bH[4][2], bL[4][2];
#pragma unroll
            for (int mi = 0; mi < 2; mi++) {
                uint32_t off = aOff0 + (uint32_t)(mi * 16 * SA2 * 2);
                ldsm_x4(aH[mi][0], aH[mi][1], aH[mi][2], aH[mi][3], aHb + off);
                ldsm_x4(aL[mi][0], aL[mi][1], aL[mi][2], aL[mi][3], aLb + off);
            }
#pragma unroll
            for (int q = 0; q < 2; q++) {
                uint32_t off = (uint32_t)(((bRowL + kh * 16) * SB_STR + bColL + q * 16) * 2);
                ldsm_x4t(bH[2 * q][0], bH[2 * q][1], bH[2 * q + 1][0], bH[2 * q + 1][1],
                         bHb + off);
                ldsm_x4t(bL[2 * q][0], bL[2 * q][1], bL[2 * q + 1][0], bL[2 * q + 1][1],
                         bLb + off);
            }
#pragma unroll
            for (int mi = 0; mi < 2; mi++)
#pragma unroll
                for (int ni = 0; ni < 4; ni++) {
                    mma16816(acc[mi][ni], aH[mi], bH[ni]);
                    mma16816(acc[mi][ni], aH[mi], bL[ni]);
                    mma16816(acc[mi][ni], aL[mi], bH[ni]);
                }
        }
        if (more) asm volatile("cp.async.wait_group 0;\n");
        __syncthreads();
    }

    // ---- epilogue ----
    int g = lane >> 2, t4 = lane & 3;
#pragma unroll
    for (int mi = 0; mi < 2; mi++) {
#pragma unroll
        for (int ni = 0; ni < 4; ni++) {
            int row0 = o0 + wo * 32 + mi * 16 + g;
            int row1 = row0 + 8;
            int col = l0 + wl * 32 + ni * 8 + t4 * 2;
            float b0 = bias_per_batch ? bias[b * O + row0] : bias[row0];
            float b1 = bias_per_batch ? bias[b * O + row1] : bias[row1];
            float v00 = acc[mi][ni][0] + b0, v01 = acc[mi][ni][1] + b0;
            float v10 = acc[mi][ni][2] + b1, v11 = acc[mi][ni][3] + b1;
            if (!final_mode) {
                float* y0 = Y + (size_t)b * O * LL + (size_t)row0 * LL + col;
                float* y1 = Y + (size_t)b * O * LL + (size_t)row1 * LL + col;
                *(float2*)y0 = make_float2(v00, v01);
                *(float2*)y1 = make_float2(v10, v11);
            } else {
                const float s = 0.70710678118654752f;
                {
                    int o = row0;
                    if (o < CC) {
                        size_t idx = (size_t)(b * CC + o) * LL + col;
                        float2 xv = *(const float2*)(xres + idx);
                        *(float2*)(Y + idx) = make_float2((xv.x + v00) * s, (xv.y + v01) * s);
                    } else {
                        size_t idx = (size_t)BB * CC * LL + (size_t)(b * CC + (o - CC)) * LL + col;
                        *(float2*)(Y + idx) = make_float2(v00, v01);
                    }
                }
                {
                    int o = row1;
                    if (o < CC) {
                        size_t idx = (size_t)(b * CC + o) * LL + col;
                        float2 xv = *(const float2*)(xres + idx);
                        *(float2*)(Y + idx) = make_float2((xv.x + v10) * s, (xv.y + v11) * s);
                    } else {
                        size_t idx = (size_t)BB * CC * LL + (size_t)(b * CC + (o - CC)) * LL + col;
                        *(float2*)(Y + idx) = make_float2(v10, v11);
                    }
                }
            }
        }
    }
#undef STAGE
}

// ---------------- fused GLU + LayerNorm (+ optional act -> bf16), LT=32 ----------------
#define LT 32
#define GLULN_SMEM ((HH * (LT + 1) + 2 * 8 * (LT + 1) + 2 * LT) * 4)

__global__ void k_gluln(const float* __restrict__ t, float* __restrict__ u,
                        __nv_bfloat16* __restrict__ zh, __nv_bfloat16* __restrict__ zl,
                        const float* __restrict__ g, const float* __restrict__ be,
                        int act_mode) {
    extern __shared__ __align__(16) float fsm[];
    float* sv = fsm;
    float* red0 = sv + HH * (LT + 1);
    float* red1 = red0 + 8 * (LT + 1);
    float* smu = red1 + 8 * (LT + 1);
    float* srs = smu + LT;

    int b = blockIdx.y, l0 = blockIdx.x * LT;
    const float* tb = t + (size_t)b * H2 * LL;
    for (int i = threadIdx.x; i < HH * LT; i += 256) {
        int h = i >> 5, l = i & (LT - 1);
        float a = tb[(size_t)h * LL + l0 + l];
        float gg = tb[(size_t)(h + HH) * LL + l0 + l];
        sv[h * (LT + 1) + l] = a * sigf(gg);
    }
    __syncthreads();
    {
        int col = threadIdx.x & (LT - 1);
        int part = threadIdx.x >> 5;
        float s = 0.f, ss = 0.f;
        for (int h = part; h < HH; h += 8) {
            float v = sv[h * (LT + 1) + col];
            s += v;
            ss = fmaf(v, v, ss);
        }
        red0[part * (LT + 1) + col] = s;
        red1[part * (LT + 1) + col] = ss;
        __syncthreads();
        if (part == 0) {
            float S = 0.f, SS = 0.f;
#pragma unroll
            for (int p = 0; p < 8; p++) {
                S += red0[p * (LT + 1) + col];
                SS += red1[p * (LT + 1) + col];
            }
            float mu = S * (1.f / HH);
            float var = SS * (1.f / HH) - mu * mu;
            smu[col] = mu;
            srs[col] = rsqrtf(var + 1e-5f);
        }
        __syncthreads();
    }
    if (!act_mode) {
        float* ub = u + (size_t)b * HH * LL;
        for (int i = threadIdx.x; i < HH * LT; i += 256) {
            int h = i >> 5, l = i & (LT - 1);
            ub[(size_t)h * LL + l0 + l] =
                (sv[h * (LT + 1) + l] - smu[l]) * srs[l] * __ldg(g + h) + __ldg(be + h);
        }
    } else {
        for (int i = threadIdx.x; i < CC * LT; i += 256) {
            int l = i & (LT - 1), h = i >> 5;
            float n0 = (sv[h * (LT + 1) + l] - smu[l]) * srs[l] * __ldg(g + h) + __ldg(be + h);
            float n1 = (sv[(h + CC) * (LT + 1) + l] - smu[l]) * srs[l] * __ldg(g + h + CC) +
                       __ldg(be + h + CC);
            float z = sigf(n0) * tanh_fast(n1);
            __nv_bfloat16 hh = __float2bfloat16(z);
            size_t idx = (size_t)(b * CC + h) * LL + l0 + l;
            zh[idx] = hh;
            zl[idx] = __float2bfloat16(z - __bfloat162float(hh));
        }
    }
}

// ---------------- launch ----------------
extern "C" void kernel_launch(void* const* d_in, const int* in_sizes, int n_in,
                              void* d_out, int out_size) {
    const float* x    = (const float*)d_in[0];
    const float* demb = (const float*)d_in[1];
    const float* dpW  = (const float*)d_in[2];
    const float* dpb  = (const float*)d_in[3];
    const float* inW  = (const float*)d_in[4];
    const float* inb  = (const float*)d_in[5];
    const float* outW = (const float*)d_in[6];
    const float* outb = (const float*)d_in[7];
    const float* ln1g = (const float*)d_in[8];
    const float* ln1b = (const float*)d_in[9];
    const float* ln2g = (const float*)d_in[10];
    const float* ln2b = (const float*)d_in[11];
    const float* s1_logdt = (const float*)d_in[12];
    const float* s1_Are   = (const float*)d_in[13];
    const float* s1_Aim   = (const float*)d_in[14];
    const float* s1_Cre   = (const float*)d_in[15];
    const float* s1_Cim   = (const float*)d_in[16];
    const float* s1_D     = (const float*)d_in[17];
    const float* s1_oW    = (const float*)d_in[18];
    const float* s1_ob    = (const float*)d_in[19];
    const float* s2_logdt = (const float*)d_in[20];
    const float* s2_Are   = (const float*)d_in[21];
    const float* s2_Aim   = (const float*)d_in[22];
    const float* s2_Cre   = (const float*)d_in[23];
    const float* s2_Cim   = (const float*)d_in[24];
    const float* s2_D     = (const float*)d_in[25];
    const float* s2_oW    = (const float*)d_in[26];
    const float* s2_ob    = (const float*)d_in[27];

    float* out = (float*)d_out;

    float *du, *dt, *de;
    __nv_bfloat16 *bh, *bl, *wh, *wlp;
    cudaGetSymbolAddress((void**)&du, g_u);
    cudaGetSymbolAddress((void**)&dt, g_t);
    cudaGetSymbolAddress((void**)&de, g_e);
    cudaGetSymbolAddress((void**)&bh, g_bh);
    cudaGetSymbolAddress((void**)&bl, g_bl);
    cudaGetSymbolAddress((void**)&wh, g_wh);
    cudaGetSymbolAddress((void**)&wlp, g_wl);

    static int attr_set = 0;
    if (!attr_set) {
        cudaFuncSetAttribute(k_gemm_bf, cudaFuncAttributeMaxDynamicSharedMemorySize, GEMM_SMEM);
        cudaFuncSetAttribute(k_gluln, cudaFuncAttributeMaxDynamicSharedMemorySize, GLULN_SMEM);
        attr_set = 1;
    }

    // 1: all conversions (weights + x)
    k_conv<<<(WTOT / 4 + XTOT / 4) / 256, 256>>>(inW, s1_oW, s2_oW, outW, x, wh, wlp, bh, bl);
    // 2: diffusion bias
    k_debias<<<BB, 256>>>(demb, dpW, dpb, inW, inb, de);
    // 3: in-proj GEMM
    k_gemm_bf<<<dim3(LL / 128, HH / 64, BB), 256, GEMM_SMEM>>>(
        wh + W1_OFF, wlp + W1_OFF, bh, bl, de, 1, du, HH, CC, nullptr, 0);
    // 4: PROFILED — S4 layer 1 SSM (2 seqs/warp -> 4096 warps)
    k_ssm<<<(BB * HH) / 8, 128>>>(du, bh, bl, s1_logdt, s1_Are, s1_Aim, s1_Cre, s1_Cim, s1_D);
    k_gemm_bf<<<dim3(LL / 128, H2 / 64, BB), 256, GEMM_SMEM>>>(
        wh + W2_OFF, wlp + W2_OFF, bh, bl, s1_ob, 0, dt, H2, HH, nullptr, 0);
    k_gluln<<<dim3(LL / LT, BB), 256, GLULN_SMEM>>>(dt, du, nullptr, nullptr, ln1g, ln1b, 0);
    // S4 layer 2
    k_ssm<<<(BB * HH) / 8, 128>>>(du, bh, bl, s2_logdt, s2_Are, s2_Aim, s2_Cre, s2_Cim, s2_D);
    k_gemm_bf<<<dim3(LL / 128, H2 / 64, BB), 256, GEMM_SMEM>>>(
        wh + W3_OFF, wlp + W3_OFF, bh, bl, s2_ob, 0, dt, H2, HH, nullptr, 0);
    // GLU+LN2+act fused -> bf16 gate/filter product
    k_gluln<<<dim3(LL / LT, BB), 256, GLULN_SMEM>>>(dt, nullptr, bh, bl, ln2g, ln2b, 1);
    // out-proj fused with residual/skip split
    k_gemm_bf<<<dim3(LL / 128, HH / 64, BB), 256, GEMM_SMEM>>>(
        wh + W4_OFF, wlp + W4_OFF, bh, bl, outb, 0, out, HH, CC, x, 1);
}

// round 16
// speedup vs baseline: 1.1302x; 1.1302x over previous
#include <cuda_runtime.h>
#include <cuda_bf16.h>
#include <math.h>
#include <stdint.h>

#define BB 16
#define CC 256
#define LL 2048
#define EE 512
#define NN 64
#define HH 512
#define H2 1024

// weight offsets in bf16 scratch (cumulative)
#define W1_OFF 0
#define W2_OFF 131072
#define W3_OFF 655360
#define W4_OFF 1179648
#define WTOT   1310720
#define XTOT   (BB * CC * LL)

// ---------------- scratch ----------------
__device__ float          g_e[BB * HH];
__device__ float          g_u[BB * HH * LL];
__device__ float          g_t[(size_t)BB * H2 * LL];
__device__ __nv_bfloat16  g_bh[BB * HH * LL];
__device__ __nv_bfloat16  g_bl[BB * HH * LL];
__device__ __nv_bfloat16  g_wh[WTOT];
__device__ __nv_bfloat16  g_wl[WTOT];

// ---------------- math helpers ----------------
__device__ __forceinline__ float sigf(float x) {
    return __fdividef(1.f, 1.f + __expf(-x));
}
__device__ __forceinline__ float tanh_fast(float x) {
    return fmaf(2.f, __fdividef(1.f, 1.f + __expf(-2.f * x)), -1.f);
}
__device__ __forceinline__ float geluf(float x) {
    // tanh-approx GELU with HW tanh (sm_75+ MUFU)
    float t = x * fmaf(0.044715f, x * x, 1.f);
    float th;
    asm("tanh.approx.f32 %0, %1;" : "=f"(th) : "f"(0.7978845608028654f * t));
    float hx = 0.5f * x;
    return fmaf(hx, th, hx);
}
__device__ __forceinline__ uint32_t pack_bf16(__nv_bfloat16 a, __nv_bfloat16 b) {
    __nv_bfloat162 v(a, b);
    return *(uint32_t*)&v;
}
// fast hi/lo bf16 split: 2 cvt + shift/mask/sub (math identical to scalar rn split)
__device__ __forceinline__ void split2(float v0, float v1, uint32_t& hi, uint32_t& lo) {
    uint32_t h;
    asm("cvt.rn.satfinite.bf16x2.f32 %0, %1, %2;" : "=r"(h) : "f"(v1), "f"(v0));
    float f0 = __uint_as_float(h << 16);
    float f1 = __uint_as_float(h & 0xffff0000u);
    float r0 = v0 - f0, r1 = v1 - f1;
    asm("cvt.rn.satfinite.bf16x2.f32 %0, %1, %2;" : "=r"(lo) : "f"(r1), "f"(r0));
    hi = h;
}

// ---------------- packed f32x2 ----------------
__device__ __forceinline__ uint64_t packf2(float lo, float hi) {
    uint64_t r;
    asm("mov.b64 %0, {%1,%2};" : "=l"(r) : "f"(lo), "f"(hi));
    return r;
}
__device__ __forceinline__ void unpackf2(uint64_t v, float& lo, float& hi) {
    asm("mov.b64 {%0,%1}, %2;" : "=f"(lo), "=f"(hi) : "l"(v));
}
__device__ __forceinline__ uint64_t fma2(uint64_t a, uint64_t b, uint64_t c) {
    uint64_t d;
    asm("fma.rn.f32x2 %0, %1, %2, %3;" : "=l"(d) : "l"(a), "l"(b), "l"(c));
    return d;
}
__device__ __forceinline__ uint64_t mul2(uint64_t a, uint64_t b) {
    uint64_t d;
    asm("mul.rn.f32x2 %0, %1, %2;" : "=l"(d) : "l"(a), "l"(b));
    return d;
}

// ---------------- fused conversion: all weights + x -> bf16 hi/lo ----------------
__global__ void k_conv(const float* __restrict__ w0, const float* __restrict__ w1,
                       const float* __restrict__ w2, const float* __restrict__ w3,
                       const float* __restrict__ x,
                       __nv_bfloat16* __restrict__ wh, __nv_bfloat16* __restrict__ wl,
                       __nv_bfloat16* __restrict__ xh, __nv_bfloat16* __restrict__ xl) {
    int i4 = blockIdx.x * 256 + threadIdx.x;
    float4 v;
    __nv_bfloat16 *oh, *ol;
    size_t off;
    if (i4 < WTOT / 4) {
        int i = i4 * 4;
        const float* src;
        if (i < W2_OFF) src = w0 + i;
        else if (i < W3_OFF) src = w1 + (i - W2_OFF);
        else if (i < W4_OFF) src = w2 + (i - W3_OFF);
        else src = w3 + (i - W4_OFF);
        v = *(const float4*)src;
        oh = wh; ol = wl; off = (size_t)i;
    } else {
        size_t i = (size_t)(i4 - WTOT / 4) * 4;
        v = *(const float4*)(x + i);
        oh = xh; ol = xl; off = i;
    }
    uint2 h, l;
    split2(v.x, v.y, h.x, l.x);
    split2(v.z, v.w, h.y, l.y);
    *(uint2*)(oh + off) = h;
    *(uint2*)(ol + off) = l;
}

// ---------------- fused diffusion proj + input bias ----------------
__global__ void k_debias(const float* __restrict__ demb, const float* __restrict__ dpW,
                         const float* __restrict__ dpb, const float* __restrict__ inW,
                         const float* __restrict__ inb, float* __restrict__ e) {
    int b = blockIdx.x;
    int t = threadIdx.x;
    __shared__ float se[EE];
    __shared__ float sd[CC];
    for (int i = t; i < EE; i += 256) se[i] = demb[b * EE + i];
    __syncthreads();
    {
        float acc = 0.f;
#pragma unroll 8
        for (int k = 0; k < EE; k++) acc = fmaf(dpW[(size_t)t * EE + k], se[k], acc);
        sd[t] = acc + dpb[t];
    }
    __syncthreads();
    for (int o = t; o < HH; o += 256) {
        float acc = 0.f;
#pragma unroll 8
        for (int k = 0; k < CC; k++) acc = fmaf(inW[(size_t)o * CC + k], sd[k], acc);
        e[b * HH + o] = acc + inb[o];
    }
}

// ---------------- diagonal SSM recurrence (prec fused) + D-skip + GELU -> bf16 hi/lo ----------------
// 4 sequences per warp (8 lanes each); prefetch ring depth 4; batched shfl reductions.
__global__ void k_ssm(const float* __restrict__ in, __nv_bfloat16* __restrict__ outh,
                      __nv_bfloat16* __restrict__ outl,
                      const float* __restrict__ log_dt, const float* __restrict__ Are,
                      const float* __restrict__ Aim, const float* __restrict__ Cre,
                      const float* __restrict__ Cim, const float* __restrict__ Dv) {
    int warpId = (blockIdx.x * blockDim.x + threadIdx.x) >> 5;
    int lane = threadIdx.x & 31;
    int sub = lane >> 3;
    int ll = lane & 7;
    int seq = warpId * 4 + sub;
    int b = seq >> 9, h = seq & (HH - 1);

    // fused precompute: z = exp(dt*A), ct = 2*C*(z-1)/A for my 8 states
    float dt = expf(log_dt[h]);
    uint64_t zr[4], zi[4], nzi[4], cr[4], nci[4];
#pragma unroll
    for (int g = 0; g < 4; g++) {
        float zrv[2], ziv[2], ctr[2], cti[2];
#pragma unroll
        for (int q = 0; q < 2; q++) {
            int idx = h * NN + ll * 8 + 2 * g + q;
            float A_r = Are[idx], A_i = Aim[idx];
            float er = expf(A_r * dt);
            float s, c0;
            sincosf(A_i * dt, &s, &c0);
            float zrr = er * c0, zii = er * s;
            float wr = zrr - 1.f, wi = zii;
            float inv = 1.f / (A_r * A_r + A_i * A_i);
            float qr = (wr * A_r + wi * A_i) * inv;
            float qi = (wi * A_r - wr * A_i) * inv;
            float crv = Cre[idx], civ = Cim[idx];
            ctr[q] = 2.f * (crv * qr - civ * qi);
            cti[q] = 2.f * (crv * qi + civ * qr);
            zrv[q] = zrr;
            ziv[q] = zii;
        }
        zr[g] = packf2(zrv[0], zrv[1]);
        zi[g] = packf2(ziv[0], ziv[1]);
        nzi[g] = packf2(-ziv[0], -ziv[1]);
        cr[g] = packf2(ctr[0], ctr[1]);
        nci[g] = packf2(-cti[0], -cti[1]);
    }
    float Dh = Dv[h];

    const float4* ip = (const float4*)(in + (size_t)(b * HH + h) * LL);
    __nv_bfloat16* oph = outh + (size_t)(b * HH + h) * LL;
    __nv_bfloat16* opl = outl + (size_t)(b * HH + h) * LL;

    uint64_t sr[4], si[4];
#pragma unroll
    for (int g = 0; g < 4; g++) { sr[g] = packf2(0.f, 0.f); si[g] = sr[g]; }

    float4 buf[4];
#pragma unroll
    for (int i = 0; i < 4; i++) buf[i] = __ldg(ip + i);

#pragma unroll 4
    for (int l4 = 0; l4 < LL / 4; l4++) {
        float4 u4 = buf[l4 & 3];
        if (l4 + 4 < LL / 4) buf[l4 & 3] = __ldg(ip + l4 + 4);
        float pj[4];
#pragma unroll
        for (int j = 0; j < 4; j++) {
            float u = (j == 0) ? u4.x : (j == 1) ? u4.y : (j == 2) ? u4.z : u4.w;
            uint64_t uu = packf2(u, u);
#pragma unroll
            for (int g = 0; g < 4; g++) {
                uint64_t tg = fma2(nzi[g], si[g], uu);
                uint64_t mg = mul2(zi[g], sr[g]);
                sr[g] = fma2(zr[g], sr[g], tg);
                si[g] = fma2(zr[g], si[g], mg);
            }
            uint64_t acc = mul2(nci[0], si[0]);
            acc = fma2(cr[0], sr[0], acc);
#pragma unroll
            for (int g = 1; g < 4; g++) {
                acc = fma2(nci[g], si[g], acc);
                acc = fma2(cr[g], sr[g], acc);
            }
            float pl, ph;
            unpackf2(acc, pl, ph);
            pj[j] = pl + ph;
        }
        // batched butterfly: 4 independent shfl chains per level
#pragma unroll
        for (int off = 4; off; off >>= 1) {
            pj[0] += __shfl_xor_sync(0xffffffffu, pj[0], off);
            pj[1] += __shfl_xor_sync(0xffffffffu, pj[1], off);
            pj[2] += __shfl_xor_sync(0xffffffffu, pj[2], off);
            pj[3] += __shfl_xor_sync(0xffffffffu, pj[3], off);
        }
        float g0 = geluf(fmaf(Dh, u4.x, pj[0]));
        float g1 = geluf(fmaf(Dh, u4.y, pj[1]));
        float g2 = geluf(fmaf(Dh, u4.z, pj[2]));
        float g3 = geluf(fmaf(Dh, u4.w, pj[3]));
        uint2 hv, lv;
        split2(g0, g1, hv.x, lv.x);
        split2(g2, g3, hv.y, lv.y);
        if (ll == 0) {
            *(uint2*)(oph + l4 * 4) = hv;
            *(uint2*)(opl + l4 * 4) = lv;
        }
    }
}

// ======================================================================
// pure-bf16 split GEMM, block 64(O)x128(L), K-chunk 32, 3 CTAs/SM
// ======================================================================
#define SA2 40
#define SB_STR 136
#define A_ELE (64 * SA2)
#define B_ELE (32 * SB_STR)
#define GEMM_SMEM ((4 * A_ELE + 4 * B_ELE) * 2)   /* 55296 bytes */

__device__ __forceinline__ void cp16(uint32_t dst, const void* src) {
    asm volatile("cp.async.ca.shared.global [%0], [%1], 16;\n" :: "r"(dst), "l"(src));
}
__device__ __forceinline__ void ldsm_x4(uint32_t& r0, uint32_t& r1, uint32_t& r2,
                                        uint32_t& r3, uint32_t addr) {
    asm volatile("ldmatrix.sync.aligned.m8n8.x4.shared.b16 {%0,%1,%2,%3}, [%4];"
                 : "=r"(r0), "=r"(r1), "=r"(r2), "=r"(r3) : "r"(addr));
}
__device__ __forceinline__ void ldsm_x4t(uint32_t& r0, uint32_t& r1, uint32_t& r2,
                                         uint32_t& r3, uint32_t addr) {
    asm volatile("ldmatrix.sync.aligned.m8n8.x4.trans.shared.b16 {%0,%1,%2,%3}, [%4];"
                 : "=r"(r0), "=r"(r1), "=r"(r2), "=r"(r3) : "r"(addr));
}
__device__ __forceinline__ void mma16816(float* c, const uint32_t* a, const uint32_t* b) {
    asm volatile("mma.sync.aligned.m16n8k16.row.col.f32.bf16.bf16.f32 "
                 "{%0,%1,%2,%3}, {%4,%5,%6,%7}, {%8,%9}, {%0,%1,%2,%3};"
                 : "+f"(c[0]), "+f"(c[1]), "+f"(c[2]), "+f"(c[3])
                 : "r"(a[0]), "r"(a[1]), "r"(a[2]), "r"(a[3]), "r"(b[0]), "r"(b[1]));
}

__global__ __launch_bounds__(256, 3)
void k_gemm_bf(const __nv_bfloat16* __restrict__ Ah_, const __nv_bfloat16* __restrict__ Al_,
               const __nv_bfloat16* __restrict__ Bh_, const __nv_bfloat16* __restrict__ Bl_,
               const float* __restrict__ bias, int bias_per_batch,
               float* __restrict__ Y, int O, int K,
               const float* __restrict__ xres, int final_mode) {
    extern __shared__ __align__(16) __nv_bfloat16 dsm[];
    __nv_bfloat16* sAh = dsm;
    __nv_bfloat16* sAl = sAh + 2 * A_ELE;
    __nv_bfloat16* sBh = sAl + 2 * A_ELE;
    __nv_bfloat16* sBl = sBh + 2 * B_ELE;

    int t = threadIdx.x, lane = t & 31, warp = t >> 5;
    int wo = warp >> 2, wl = warp & 3;
    int o0 = blockIdx.y * 64, l0 = blockIdx.x * 128, b = blockIdx.z;
    const __nv_bfloat16* BhB = Bh_ + (size_t)b * K * LL;
    const __nv_bfloat16* BlB = Bl_ + (size_t)b * K * LL;
    int nk = K / 32;

    float acc[2][4][4];
#pragma unroll
    for (int i = 0; i < 2; i++)
#pragma unroll
        for (int j = 0; j < 4; j++)
#pragma unroll
            for (int q = 0; q < 4; q++) acc[i][j][q] = 0.f;

#define STAGE(buf, kb)                                                                     \
    do {                                                                                   \
        {                                                                                  \
            int arow = t >> 2, acs = (t & 3) * 8;                                          \
            cp16((uint32_t)__cvta_generic_to_shared(                                       \
                     sAh + (buf) * A_ELE + arow * SA2 + acs),                              \
                 Ah_ + (size_t)(o0 + arow) * K + (kb) + acs);                              \
            cp16((uint32_t)__cvta_generic_to_shared(                                       \
                     sAl + (buf) * A_ELE + arow * SA2 + acs),                              \
                 Al_ + (size_t)(o0 + arow) * K + (kb) + acs);                              \
        }                                                                                  \
        _Pragma("unroll")                                                                  \
        for (int q = 0; q < 2; q++) {                                                      \
            int idx = q * 256 + t;                                                         \
            int brow = idx >> 4, bcs = (idx & 15) * 8;                                     \
            cp16((uint32_t)__cvta_generic_to_shared(                                       \
                     sBh + (buf) * B_ELE + brow * SB_STR + bcs),                           \
                 BhB + (size_t)((kb) + brow) * LL + l0 + bcs);                             \
            cp16((uint32_t)__cvta_generic_to_shared(                                       \
                     sBl + (buf) * B_ELE + brow * SB_STR + bcs),                           \
                 BlB + (size_t)((kb) + brow) * LL + l0 + bcs);                             \
        }                                                                                  \
        asm volatile("cp.async.commit_group;\n");                                         \
    } while (0)

    STAGE(0, 0);
    asm volatile("cp.async.wait_group 0;\n");
    __syncthreads();

    int aRowL = wo * 32 + (lane & 15);
    int aColL = (lane >> 4) * 8;
    int bRowL = lane & 15;
    int bColL = wl * 32 + (lane >> 4) * 8;

    for (int kc = 0; kc < nk; kc++) {
        int cur = kc & 1;
        bool more = (kc + 1) < nk;
        if (more) STAGE(cur ^ 1, (kc + 1) * 32);

        uint32_t aHb = (uint32_t)__cvta_generic_to_shared(sAh + cur * A_ELE);
        uint32_t aLb = (uint32_t)__cvta_generic_to_shared(sAl + cur * A_ELE);
        uint32_t bHb = (uint32_t)__cvta_generic_to_shared(sBh + cur * B_ELE);
        uint32_t bLb = (uint32_t)__cvta_generic_to_shared(sBl + cur * B_ELE);

#pragma unroll
        for (int kh = 0; kh < 2; kh++) {
            uint32_t aOff0 = (uint32_t)((aRowL * SA2 + aColL + kh * 16) * 2);
            uint32_t aH[2][4], aL[2][4], bH[4][2], bL[4][2];
#pragma unroll
            for (int mi = 0; mi < 2; mi++) {
                uint32_t off = aOff0 + (uint32_t)(mi * 16 * SA2 * 2);
                ldsm_x4(aH[mi][0], aH[mi][1], aH[mi][2], aH[mi][3], aHb + off);
                ldsm_x4(aL[mi][0], aL[mi][1], aL[mi][2], aL[mi][3], aLb + off);
            }
#pragma unroll
            for (int q = 0; q < 2; q++) {
                uint32_t off = (uint32_t)(((bRowL + kh * 16) * SB_STR + bColL + q * 16) * 2);
                ldsm_x4t(bH[2 * q][0], bH[2 * q][1], bH[2 * q + 1][0], bH[2 * q + 1][1],
                         bHb + off);
                ldsm_x4t(bL[2 * q][0], bL[2 * q][1], bL[2 * q + 1][0], bL[2 * q + 1][1],
                         bLb + off);
            }
#pragma unroll
            for (int mi = 0; mi < 2; mi++)
#pragma unroll
                for (int ni = 0; ni < 4; ni++) {
                    mma16816(acc[mi][ni], aH[mi], bH[ni]);
                    mma16816(acc[mi][ni], aH[mi], bL[ni]);
                    mma16816(acc[mi][ni], aL[mi], bH[ni]);
                }
        }
        if (more) asm volatile("cp.async.wait_group 0;\n");
        __syncthreads();
    }

    // ---- epilogue ----
    int g = lane >> 2, t4 = lane & 3;
#pragma unroll
    for (int mi = 0; mi < 2; mi++) {
#pragma unroll
        for (int ni = 0; ni < 4; ni++) {
            int row0 = o0 + wo * 32 + mi * 16 + g;
            int row1 = row0 + 8;
            int col = l0 + wl * 32 + ni * 8 + t4 * 2;
            float b0 = bias_per_batch ? bias[b * O + row0] : bias[row0];
            float b1 = bias_per_batch ? bias[b * O + row1] : bias[row1];
            float v00 = acc[mi][ni][0] + b0, v01 = acc[mi][ni][1] + b0;
            float v10 = acc[mi][ni][2] + b1, v11 = acc[mi][ni][3] + b1;
            if (!final_mode) {
                float* y0 = Y + (size_t)b * O * LL + (size_t)row0 * LL + col;
                float* y1 = Y + (size_t)b * O * LL + (size_t)row1 * LL + col;
                *(float2*)y0 = make_float2(v00, v01);
                *(float2*)y1 = make_float2(v10, v11);
            } else {
                const float s = 0.70710678118654752f;
                {
                    int o = row0;
                    if (o < CC) {
                        size_t idx = (size_t)(b * CC + o) * LL + col;
                        float2 xv = *(const float2*)(xres + idx);
                        *(float2*)(Y + idx) = make_float2((xv.x + v00) * s, (xv.y + v01) * s);
                    } else {
                        size_t idx = (size_t)BB * CC * LL + (size_t)(b * CC + (o - CC)) * LL + col;
                        *(float2*)(Y + idx) = make_float2(v00, v01);
                    }
                }
                {
                    int o = row1;
                    if (o < CC) {
                        size_t idx = (size_t)(b * CC + o) * LL + col;
                        float2 xv = *(const float2*)(xres + idx);
                        *(float2*)(Y + idx) = make_float2((xv.x + v10) * s, (xv.y + v11) * s);
                    } else {
                        size_t idx = (size_t)BB * CC * LL + (size_t)(b * CC + (o - CC)) * LL + col;
                        *(float2*)(Y + idx) = make_float2(v10, v11);
                    }
                }
            }
        }
    }
#undef STAGE
}

// ---------------- fused GLU + LayerNorm (+ optional act -> bf16), LT=32 ----------------
#define LT 32
#define GLULN_SMEM ((HH * (LT + 1) + 2 * 8 * (LT + 1) + 2 * LT) * 4)

__global__ void k_gluln(const float* __restrict__ t, float* __restrict__ u,
                        __nv_bfloat16* __restrict__ zh, __nv_bfloat16* __restrict__ zl,
                        const float* __restrict__ g, const float* __restrict__ be,
                        int act_mode) {
    extern __shared__ __align__(16) float fsm[];
    float* sv = fsm;
    float* red0 = sv + HH * (LT + 1);
    float* red1 = red0 + 8 * (LT + 1);
    float* smu = red1 + 8 * (LT + 1);
    float* srs = smu + LT;

    int b = blockIdx.y, l0 = blockIdx.x * LT;
    const float* tb = t + (size_t)b * H2 * LL;
    for (int i = threadIdx.x; i < HH * LT; i += 256) {
        int h = i >> 5, l = i & (LT - 1);
        float a = tb[(size_t)h * LL + l0 + l];
        float gg = tb[(size_t)(h + HH) * LL + l0 + l];
        sv[h * (LT + 1) + l] = a * sigf(gg);
    }
    __syncthreads();
    {
        int col = threadIdx.x & (LT - 1);
        int part = threadIdx.x >> 5;
        float s = 0.f, ss = 0.f;
        for (int h = part; h < HH; h += 8) {
            float v = sv[h * (LT + 1) + col];
            s += v;
            ss = fmaf(v, v, ss);
        }
        red0[part * (LT + 1) + col] = s;
        red1[part * (LT + 1) + col] = ss;
        __syncthreads();
        if (part == 0) {
            float S = 0.f, SS = 0.f;
#pragma unroll
            for (int p = 0; p < 8; p++) {
                S += red0[p * (LT + 1) + col];
                SS += red1[p * (LT + 1) + col];
            }
            float mu = S * (1.f / HH);
            float var = SS * (1.f / HH) - mu * mu;
            smu[col] = mu;
            srs[col] = rsqrtf(var + 1e-5f);
        }
        __syncthreads();
    }
    if (!act_mode) {
        float* ub = u + (size_t)b * HH * LL;
        for (int i = threadIdx.x; i < HH * LT; i += 256) {
            int h = i >> 5, l = i & (LT - 1);
            ub[(size_t)h * LL + l0 + l] =
                (sv[h * (LT + 1) + l] - smu[l]) * srs[l] * __ldg(g + h) + __ldg(be + h);
        }
    } else {
        for (int i = threadIdx.x; i < CC * LT; i += 256) {
            int l = i & (LT - 1), h = i >> 5;
            float n0 = (sv[h * (LT + 1) + l] - smu[l]) * srs[l] * __ldg(g + h) + __ldg(be + h);
            float n1 = (sv[(h + CC) * (LT + 1) + l] - smu[l]) * srs[l] * __ldg(g + h + CC) +
                       __ldg(be + h + CC);
            float z = sigf(n0) * tanh_fast(n1);
            __nv_bfloat16 hh = __float2bfloat16(z);
            size_t idx = (size_t)(b * CC + h) * LL + l0 + l;
            zh[idx] = hh;
            zl[idx] = __float2bfloat16(z - __bfloat162float(hh));
        }
    }
}

// ---------------- launch ----------------
extern "C" void kernel_launch(void* const* d_in, const int* in_sizes, int n_in,
                              void* d_out, int out_size) {
    const float* x    = (const float*)d_in[0];
    const float* demb = (const float*)d_in[1];
    const float* dpW  = (const float*)d_in[2];
    const float* dpb  = (const float*)d_in[3];
    const float* inW  = (const float*)d_in[4];
    const float* inb  = (const float*)d_in[5];
    const float* outW = (const float*)d_in[6];
    const float* outb = (const float*)d_in[7];
    const float* ln1g = (const float*)d_in[8];
    const float* ln1b = (const float*)d_in[9];
    const float* ln2g = (const float*)d_in[10];
    const float* ln2b = (const float*)d_in[11];
    const float* s1_logdt = (const float*)d_in[12];
    const float* s1_Are   = (const float*)d_in[13];
    const float* s1_Aim   = (const float*)d_in[14];
    const float* s1_Cre   = (const float*)d_in[15];
    const float* s1_Cim   = (const float*)d_in[16];
    const float* s1_D     = (const float*)d_in[17];
    const float* s1_oW    = (const float*)d_in[18];
    const float* s1_ob    = (const float*)d_in[19];
    const float* s2_logdt = (const float*)d_in[20];
    const float* s2_Are   = (const float*)d_in[21];
    const float* s2_Aim   = (const float*)d_in[22];
    const float* s2_Cre   = (const float*)d_in[23];
    const float* s2_Cim   = (const float*)d_in[24];
    const float* s2_D     = (const float*)d_in[25];
    const float* s2_oW    = (const float*)d_in[26];
    const float* s2_ob    = (const float*)d_in[27];

    float* out = (float*)d_out;

    float *du, *dt, *de;
    __nv_bfloat16 *bh, *bl, *wh, *wlp;
    cudaGetSymbolAddress((void**)&du, g_u);
    cudaGetSymbolAddress((void**)&dt, g_t);
    cudaGetSymbolAddress((void**)&de, g_e);
    cudaGetSymbolAddress((void**)&bh, g_bh);
    cudaGetSymbolAddress((void**)&bl, g_bl);
    cudaGetSymbolAddress((void**)&wh, g_wh);
    cudaGetSymbolAddress((void**)&wlp, g_wl);

    static int attr_set = 0;
    if (!attr_set) {
        cudaFuncSetAttribute(k_gemm_bf, cudaFuncAttributeMaxDynamicSharedMemorySize, GEMM_SMEM);
        cudaFuncSetAttribute(k_gluln, cudaFuncAttributeMaxDynamicSharedMemorySize, GLULN_SMEM);
        attr_set = 1;
    }

    // 1: all conversions (weights + x)
    k_conv<<<(WTOT / 4 + XTOT / 4) / 256, 256>>>(inW, s1_oW, s2_oW, outW, x, wh, wlp, bh, bl);
    // 2: diffusion bias
    k_debias<<<BB, 256>>>(demb, dpW, dpb, inW, inb, de);
    // 3: in-proj GEMM
    k_gemm_bf<<<dim3(LL / 128, HH / 64, BB), 256, GEMM_SMEM>>>(
        wh + W1_OFF, wlp + W1_OFF, bh, bl, de, 1, du, HH, CC, nullptr, 0);
    // 4: PROFILED — S4 layer 1 SSM
    k_ssm<<<(BB * HH) / 16, 128>>>(du, bh, bl, s1_logdt, s1_Are, s1_Aim, s1_Cre, s1_Cim, s1_D);
    k_gemm_bf<<<dim3(LL / 128, H2 / 64, BB), 256, GEMM_SMEM>>>(
        wh + W2_OFF, wlp + W2_OFF, bh, bl, s1_ob, 0, dt, H2, HH, nullptr, 0);
    k_gluln<<<dim3(LL / LT, BB), 256, GLULN_SMEM>>>(dt, du, nullptr, nullptr, ln1g, ln1b, 0);
    // S4 layer 2
    k_ssm<<<(BB * HH) / 16, 128>>>(du, bh, bl, s2_logdt, s2_Are, s2_Aim, s2_Cre, s2_Cim, s2_D);
    k_gemm_bf<<<dim3(LL / 128, H2 / 64, BB), 256, GEMM_SMEM>>>(
        wh + W3_OFF, wlp + W3_OFF, bh, bl, s2_ob, 0, dt, H2, HH, nullptr, 0);
    // GLU+LN2+act fused -> bf16 gate/filter product
    k_gluln<<<dim3(LL / LT, BB), 256, GLULN_SMEM>>>(dt, nullptr, bh, bl, ln2g, ln2b, 1);
    // out-proj fused with residual/skip split
    k_gemm_bf<<<dim3(LL / 128, HH / 64, BB), 256, GEMM_SMEM>>>(
        wh + W4_OFF, wlp + W4_OFF, bh, bl, outb, 0, out, HH, CC, x, 1);
}

// round 17
// speedup vs baseline: 1.1353x; 1.0045x over previous
#include <cuda_runtime.h>
#include <cuda_bf16.h>
#include <math.h>
#include <stdint.h>

#define BB 16
#define CC 256
#define LL 2048
#define EE 512
#define NN 64
#define HH 512
#define H2 1024

// weight offsets in bf16 scratch (cumulative)
#define W1_OFF 0
#define W2_OFF 131072
#define W3_OFF 655360
#define W4_OFF 1179648
#define WTOT   1310720
#define XTOT   (BB * CC * LL)

// ---------------- scratch ----------------
__device__ float          g_e[BB * HH];
__device__ float          g_u[BB * HH * LL];
__device__ float          g_t[(size_t)BB * H2 * LL];
__device__ __nv_bfloat16  g_bh[BB * HH * LL];
__device__ __nv_bfloat16  g_bl[BB * HH * LL];
__device__ __nv_bfloat16  g_wh[WTOT];
__device__ __nv_bfloat16  g_wl[WTOT];

// ---------------- math helpers ----------------
__device__ __forceinline__ float tanh_mufu(float x) {
    float t;
    asm("tanh.approx.f32 %0, %1;" : "=f"(t) : "f"(x));
    return t;
}
__device__ __forceinline__ float sigf(float x) {
    return fmaf(0.5f, tanh_mufu(0.5f * x), 0.5f);
}
__device__ __forceinline__ float geluf(float x) {
    float t = x * fmaf(0.044715f, x * x, 1.f);
    float th = tanh_mufu(0.7978845608028654f * t);
    float hx = 0.5f * x;
    return fmaf(hx, th, hx);
}
// fast hi/lo bf16 split: 2 cvt + shift/mask/sub
__device__ __forceinline__ void split2(float v0, float v1, uint32_t& hi, uint32_t& lo) {
    uint32_t h;
    asm("cvt.rn.satfinite.bf16x2.f32 %0, %1, %2;" : "=r"(h) : "f"(v1), "f"(v0));
    float f0 = __uint_as_float(h << 16);
    float f1 = __uint_as_float(h & 0xffff0000u);
    float r0 = v0 - f0, r1 = v1 - f1;
    asm("cvt.rn.satfinite.bf16x2.f32 %0, %1, %2;" : "=r"(lo) : "f"(r1), "f"(r0));
    hi = h;
}

// ---------------- packed f32x2 ----------------
__device__ __forceinline__ uint64_t packf2(float lo, float hi) {
    uint64_t r;
    asm("mov.b64 %0, {%1,%2};" : "=l"(r) : "f"(lo), "f"(hi));
    return r;
}
__device__ __forceinline__ void unpackf2(uint64_t v, float& lo, float& hi) {
    asm("mov.b64 {%0,%1}, %2;" : "=f"(lo), "=f"(hi) : "l"(v));
}
__device__ __forceinline__ uint64_t fma2(uint64_t a, uint64_t b, uint64_t c) {
    uint64_t d;
    asm("fma.rn.f32x2 %0, %1, %2, %3;" : "=l"(d) : "l"(a), "l"(b), "l"(c));
    return d;
}
__device__ __forceinline__ uint64_t mul2(uint64_t a, uint64_t b) {
    uint64_t d;
    asm("mul.rn.f32x2 %0, %1, %2;" : "=l"(d) : "l"(a), "l"(b));
    return d;
}

// ---------------- fused conversion: all weights + x -> bf16 hi/lo ----------------
__global__ void k_conv(const float* __restrict__ w0, const float* __restrict__ w1,
                       const float* __restrict__ w2, const float* __restrict__ w3,
                       const float* __restrict__ x,
                       __nv_bfloat16* __restrict__ wh, __nv_bfloat16* __restrict__ wl,
                       __nv_bfloat16* __restrict__ xh, __nv_bfloat16* __restrict__ xl) {
    int i4 = blockIdx.x * 256 + threadIdx.x;
    float4 v;
    __nv_bfloat16 *oh, *ol;
    size_t off;
    if (i4 < WTOT / 4) {
        int i = i4 * 4;
        const float* src;
        if (i < W2_OFF) src = w0 + i;
        else if (i < W3_OFF) src = w1 + (i - W2_OFF);
        else if (i < W4_OFF) src = w2 + (i - W3_OFF);
        else src = w3 + (i - W4_OFF);
        v = *(const float4*)src;
        oh = wh; ol = wl; off = (size_t)i;
    } else {
        size_t i = (size_t)(i4 - WTOT / 4) * 4;
        v = *(const float4*)(x + i);
        oh = xh; ol = xl; off = i;
    }
    uint2 h, l;
    split2(v.x, v.y, h.x, l.x);
    split2(v.z, v.w, h.y, l.y);
    *(uint2*)(oh + off) = h;
    *(uint2*)(ol + off) = l;
}

// ---------------- fused diffusion proj + input bias ----------------
__global__ void k_debias(const float* __restrict__ demb, const float* __restrict__ dpW,
                         const float* __restrict__ dpb, const float* __restrict__ inW,
                         const float* __restrict__ inb, float* __restrict__ e) {
    int b = blockIdx.x;
    int t = threadIdx.x;
    __shared__ float se[EE];
    __shared__ float sd[CC];
    for (int i = t; i < EE; i += 256) se[i] = demb[b * EE + i];
    __syncthreads();
    {
        float acc = 0.f;
#pragma unroll 8
        for (int k = 0; k < EE; k++) acc = fmaf(dpW[(size_t)t * EE + k], se[k], acc);
        sd[t] = acc + dpb[t];
    }
    __syncthreads();
    for (int o = t; o < HH; o += 256) {
        float acc = 0.f;
#pragma unroll 8
        for (int k = 0; k < CC; k++) acc = fmaf(inW[(size_t)o * CC + k], sd[k], acc);
        e[b * HH + o] = acc + inb[o];
    }
}

// ---------------- diagonal SSM recurrence (prec fused) + D-skip + GELU -> bf16 hi/lo ----------------
// 4 sequences per warp (8 lanes each); prefetch ring depth 4; batched shfl;
// epilogue software-pipelined by 1 iteration (shfl latency hidden behind next states).
__global__ void k_ssm(const float* __restrict__ in, __nv_bfloat16* __restrict__ outh,
                      __nv_bfloat16* __restrict__ outl,
                      const float* __restrict__ log_dt, const float* __restrict__ Are,
                      const float* __restrict__ Aim, const float* __restrict__ Cre,
                      const float* __restrict__ Cim, const float* __restrict__ Dv) {
    int warpId = (blockIdx.x * blockDim.x + threadIdx.x) >> 5;
    int lane = threadIdx.x & 31;
    int sub = lane >> 3;
    int ll = lane & 7;
    int seq = warpId * 4 + sub;
    int b = seq >> 9, h = seq & (HH - 1);

    // fused precompute: z = exp(dt*A), ct = 2*C*(z-1)/A for my 8 states
    float dt = expf(log_dt[h]);
    uint64_t zr[4], zi[4], nzi[4], cr[4], nci[4];
#pragma unroll
    for (int g = 0; g < 4; g++) {
        float zrv[2], ziv[2], ctr[2], cti[2];
#pragma unroll
        for (int q = 0; q < 2; q++) {
            int idx = h * NN + ll * 8 + 2 * g + q;
            float A_r = Are[idx], A_i = Aim[idx];
            float er = expf(A_r * dt);
            float s, c0;
            sincosf(A_i * dt, &s, &c0);
            float zrr = er * c0, zii = er * s;
            float wr = zrr - 1.f, wi = zii;
            float inv = 1.f / (A_r * A_r + A_i * A_i);
            float qr = (wr * A_r + wi * A_i) * inv;
            float qi = (wi * A_r - wr * A_i) * inv;
            float crv = Cre[idx], civ = Cim[idx];
            ctr[q] = 2.f * (crv * qr - civ * qi);
            cti[q] = 2.f * (crv * qi + civ * qr);
            zrv[q] = zrr;
            ziv[q] = zii;
        }
        zr[g] = packf2(zrv[0], zrv[1]);
        zi[g] = packf2(ziv[0], ziv[1]);
        nzi[g] = packf2(-ziv[0], -ziv[1]);
        cr[g] = packf2(ctr[0], ctr[1]);
        nci[g] = packf2(-cti[0], -cti[1]);
    }
    float Dh = Dv[h];

    const float4* ip = (const float4*)(in + (size_t)(b * HH + h) * LL);
    __nv_bfloat16* oph = outh + (size_t)(b * HH + h) * LL;
    __nv_bfloat16* opl = outl + (size_t)(b * HH + h) * LL;

    uint64_t sr[4], si[4];
#pragma unroll
    for (int g = 0; g < 4; g++) { sr[g] = packf2(0.f, 0.f); si[g] = sr[g]; }

    float4 buf[4];
#pragma unroll
    for (int i = 0; i < 4; i++) buf[i] = __ldg(ip + i);

    float pjp[4];       // reduced pj of previous iteration
    float4 up;          // u of previous iteration

#pragma unroll 4
    for (int l4 = 0; l4 < LL / 4; l4++) {
        float4 u4 = buf[l4 & 3];
        if (l4 + 4 < LL / 4) buf[l4 & 3] = __ldg(ip + l4 + 4);
        float pj[4];
        // state updates + in-lane dot for iteration l4
#pragma unroll
        for (int j = 0; j < 4; j++) {
            float u = (j == 0) ? u4.x : (j == 1) ? u4.y : (j == 2) ? u4.z : u4.w;
            uint64_t uu = packf2(u, u);
#pragma unroll
            for (int g = 0; g < 4; g++) {
                uint64_t tg = fma2(nzi[g], si[g], uu);
                uint64_t mg = mul2(zi[g], sr[g]);
                sr[g] = fma2(zr[g], sr[g], tg);
                si[g] = fma2(zr[g], si[g], mg);
            }
            uint64_t acc = mul2(nci[0], si[0]);
            acc = fma2(cr[0], sr[0], acc);
#pragma unroll
            for (int g = 1; g < 4; g++) {
                acc = fma2(nci[g], si[g], acc);
                acc = fma2(cr[g], sr[g], acc);
            }
            float pl, ph;
            unpackf2(acc, pl, ph);
            pj[j] = pl + ph;
        }
        // deferred epilogue for iteration l4-1 (consumes previous shfl results,
        // which have had a full iteration of state work to complete)
        if (l4 > 0) {
            float g0 = geluf(fmaf(Dh, up.x, pjp[0]));
            float g1 = geluf(fmaf(Dh, up.y, pjp[1]));
            float g2 = geluf(fmaf(Dh, up.z, pjp[2]));
            float g3 = geluf(fmaf(Dh, up.w, pjp[3]));
            uint2 hv, lv;
            split2(g0, g1, hv.x, lv.x);
            split2(g2, g3, hv.y, lv.y);
            if (ll == 0) {
                *(uint2*)(oph + (l4 - 1) * 4) = hv;
                *(uint2*)(opl + (l4 - 1) * 4) = lv;
            }
        }
        // issue reduction for iteration l4 (consumed next iteration)
#pragma unroll
        for (int off = 4; off; off >>= 1) {
            pj[0] += __shfl_xor_sync(0xffffffffu, pj[0], off);
            pj[1] += __shfl_xor_sync(0xffffffffu, pj[1], off);
            pj[2] += __shfl_xor_sync(0xffffffffu, pj[2], off);
            pj[3] += __shfl_xor_sync(0xffffffffu, pj[3], off);
        }
        pjp[0] = pj[0]; pjp[1] = pj[1]; pjp[2] = pj[2]; pjp[3] = pj[3];
        up = u4;
    }
    // final epilogue
    {
        float g0 = geluf(fmaf(Dh, up.x, pjp[0]));
        float g1 = geluf(fmaf(Dh, up.y, pjp[1]));
        float g2 = geluf(fmaf(Dh, up.z, pjp[2]));
        float g3 = geluf(fmaf(Dh, up.w, pjp[3]));
        uint2 hv, lv;
        split2(g0, g1, hv.x, lv.x);
        split2(g2, g3, hv.y, lv.y);
        if (ll == 0) {
            *(uint2*)(oph + (LL / 4 - 1) * 4) = hv;
            *(uint2*)(opl + (LL / 4 - 1) * 4) = lv;
        }
    }
}

// ======================================================================
// pure-bf16 split GEMM, block 64(O)x128(L), K-chunk 32, 3 CTAs/SM
// ======================================================================
#define SA2 40
#define SB_STR 136
#define A_ELE (64 * SA2)
#define B_ELE (32 * SB_STR)
#define GEMM_SMEM ((4 * A_ELE + 4 * B_ELE) * 2)   /* 55296 bytes */

__device__ __forceinline__ void cp16(uint32_t dst, const void* src) {
    asm volatile("cp.async.ca.shared.global [%0], [%1], 16;\n" :: "r"(dst), "l"(src));
}
__device__ __forceinline__ void ldsm_x4(uint32_t& r0, uint32_t& r1, uint32_t& r2,
                                        uint32_t& r3, uint32_t addr) {
    asm volatile("ldmatrix.sync.aligned.m8n8.x4.shared.b16 {%0,%1,%2,%3}, [%4];"
                 : "=r"(r0), "=r"(r1), "=r"(r2), "=r"(r3) : "r"(addr));
}
__device__ __forceinline__ void ldsm_x4t(uint32_t& r0, uint32_t& r1, uint32_t& r2,
                                         uint32_t& r3, uint32_t addr) {
    asm volatile("ldmatrix.sync.aligned.m8n8.x4.trans.shared.b16 {%0,%1,%2,%3}, [%4];"
                 : "=r"(r0), "=r"(r1), "=r"(r2), "=r"(r3) : "r"(addr));
}
__device__ __forceinline__ void mma16816(float* c, const uint32_t* a, const uint32_t* b) {
    asm volatile("mma.sync.aligned.m16n8k16.row.col.f32.bf16.bf16.f32 "
                 "{%0,%1,%2,%3}, {%4,%5,%6,%7}, {%8,%9}, {%0,%1,%2,%3};"
                 : "+f"(c[0]), "+f"(c[1]), "+f"(c[2]), "+f"(c[3])
                 : "r"(a[0]), "r"(a[1]), "r"(a[2]), "r"(a[3]), "r"(b[0]), "r"(b[1]));
}

__global__ __launch_bounds__(256, 3)
void k_gemm_bf(const __nv_bfloat16* __restrict__ Ah_, const __nv_bfloat16* __restrict__ Al_,
               const __nv_bfloat16* __restrict__ Bh_, const __nv_bfloat16* __restrict__ Bl_,
               const float* __restrict__ bias, int bias_per_batch,
               float* __restrict__ Y, int O, int K,
               const float* __restrict__ xres, int final_mode) {
    extern __shared__ __align__(16) __nv_bfloat16 dsm[];
    __nv_bfloat16* sAh = dsm;
    __nv_bfloat16* sAl = sAh + 2 * A_ELE;
    __nv_bfloat16* sBh = sAl + 2 * A_ELE;
    __nv_bfloat16* sBl = sBh + 2 * B_ELE;

    int t = threadIdx.x, lane = t & 31, warp = t >> 5;
    int wo = warp >> 2, wl = warp & 3;
    int o0 = blockIdx.y * 64, l0 = blockIdx.x * 128, b = blockIdx.z;
    const __nv_bfloat16* BhB = Bh_ + (size_t)b * K * LL;
    const __nv_bfloat16* BlB = Bl_ + (size_t)b * K * LL;
    int nk = K / 32;

    float acc[2][4][4];
#pragma unroll
    for (int i = 0; i < 2; i++)
#pragma unroll
        for (int j = 0; j < 4; j++)
#pragma unroll
            for (int q = 0; q < 4; q++) acc[i][j][q] = 0.f;

#define STAGE(buf, kb)                                                                     \
    do {                                                                                   \
        {                                                                                  \
            int arow = t >> 2, acs = (t & 3) * 8;                                          \
            cp16((uint32_t)__cvta_generic_to_shared(                                       \
                     sAh + (buf) * A_ELE + arow * SA2 + acs),                              \
                 Ah_ + (size_t)(o0 + arow) * K + (kb) + acs);                              \
            cp16((uint32_t)__cvta_generic_to_shared(                                       \
                     sAl + (buf) * A_ELE + arow * SA2 + acs),                              \
                 Al_ + (size_t)(o0 + arow) * K + (kb) + acs);                              \
        }                                                                                  \
        _Pragma("unroll")                                                                  \
        for (int q = 0; q < 2; q++) {                                                      \
            int idx = q * 256 + t;                                                         \
            int brow = idx >> 4, bcs = (idx & 15) * 8;                                     \
            cp16((uint32_t)__cvta_generic_to_shared(                                       \
                     sBh + (buf) * B_ELE + brow * SB_STR + bcs),                           \
                 BhB + (size_t)((kb) + brow) * LL + l0 + bcs);                             \
            cp16((uint32_t)__cvta_generic_to_shared(                                       \
                     sBl + (buf) * B_ELE + brow * SB_STR + bcs),                           \
                 BlB + (size_t)((kb) + brow) * LL + l0 + bcs);                             \
        }                                                                                  \
        asm volatile("cp.async.commit_group;\n");                                         \
    } while (0)

    STAGE(0, 0);
    asm volatile("cp.async.wait_group 0;\n");
    __syncthreads();

    int aRowL = wo * 32 + (lane & 15);
    int aColL = (lane >> 4) * 8;
    int bRowL = lane & 15;
    int bColL = wl * 32 + (lane >> 4) * 8;

    for (int kc = 0; kc < nk; kc++) {
        int cur = kc & 1;
        bool more = (kc + 1) < nk;
        if (more) STAGE(cur ^ 1, (kc + 1) * 32);

        uint32_t aHb = (uint32_t)__cvta_generic_to_shared(sAh + cur * A_ELE);
        uint32_t aLb = (uint32_t)__cvta_generic_to_shared(sAl + cur * A_ELE);
        uint32_t bHb = (uint32_t)__cvta_generic_to_shared(sBh + cur * B_ELE);
        uint32_t bLb = (uint32_t)__cvta_generic_to_shared(sBl + cur * B_ELE);

#pragma unroll
        for (int kh = 0; kh < 2; kh++) {
            uint32_t aOff0 = (uint32_t)((aRowL * SA2 + aColL + kh * 16) * 2);
            uint32_t aH[2][4], aL[2][4], bH[4][2], bL[4][2];
#pragma unroll
            for (int mi = 0; mi < 2; mi++) {
                uint32_t off = aOff0 + (uint32_t)(mi * 16 * SA2 * 2);
                ldsm_x4(aH[mi][0], aH[mi][1], aH[mi][2], aH[mi][3], aHb + off);
                ldsm_x4(aL[mi][0], aL[mi][1], aL[mi][2], aL[mi][3], aLb + off);
            }
#pragma unroll
            for (int q = 0; q < 2; q++) {
                uint32_t off = (uint32_t)(((bRowL + kh * 16) * SB_STR + bColL + q * 16) * 2);
                ldsm_x4t(bH[2 * q][0], bH[2 * q][1], bH[2 * q + 1][0], bH[2 * q + 1][1],
                         bHb + off);
                ldsm_x4t(bL[2 * q][0], bL[2 * q][1], bL[2 * q + 1][0], bL[2 * q + 1][1],
                         bLb + off);
            }
#pragma unroll
            for (int mi = 0; mi < 2; mi++)
#pragma unroll
                for (int ni = 0; ni < 4; ni++) {
                    mma16816(acc[mi][ni], aH[mi], bH[ni]);
                    mma16816(acc[mi][ni], aH[mi], bL[ni]);
                    mma16816(acc[mi][ni], aL[mi], bH[ni]);
                }
        }
        if (more) asm volatile("cp.async.wait_group 0;\n");
        __syncthreads();
    }

    // ---- epilogue ----
    int g = lane >> 2, t4 = lane & 3;
#pragma unroll
    for (int mi = 0; mi < 2; mi++) {
#pragma unroll
        for (int ni = 0; ni < 4; ni++) {
            int row0 = o0 + wo * 32 + mi * 16 + g;
            int row1 = row0 + 8;
            int col = l0 + wl * 32 + ni * 8 + t4 * 2;
            float b0 = bias_per_batch ? bias[b * O + row0] : bias[row0];
            float b1 = bias_per_batch ? bias[b * O + row1] : bias[row1];
            float v00 = acc[mi][ni][0] + b0, v01 = acc[mi][ni][1] + b0;
            float v10 = acc[mi][ni][2] + b1, v11 = acc[mi][ni][3] + b1;
            if (!final_mode) {
                float* y0 = Y + (size_t)b * O * LL + (size_t)row0 * LL + col;
                float* y1 = Y + (size_t)b * O * LL + (size_t)row1 * LL + col;
                *(float2*)y0 = make_float2(v00, v01);
                *(float2*)y1 = make_float2(v10, v11);
            } else {
                const float s = 0.70710678118654752f;
                {
                    int o = row0;
                    if (o < CC) {
                        size_t idx = (size_t)(b * CC + o) * LL + col;
                        float2 xv = *(const float2*)(xres + idx);
                        *(float2*)(Y + idx) = make_float2((xv.x + v00) * s, (xv.y + v01) * s);
                    } else {
                        size_t idx = (size_t)BB * CC * LL + (size_t)(b * CC + (o - CC)) * LL + col;
                        *(float2*)(Y + idx) = make_float2(v00, v01);
                    }
                }
                {
                    int o = row1;
                    if (o < CC) {
                        size_t idx = (size_t)(b * CC + o) * LL + col;
                        float2 xv = *(const float2*)(xres + idx);
                        *(float2*)(Y + idx) = make_float2((xv.x + v10) * s, (xv.y + v11) * s);
                    } else {
                        size_t idx = (size_t)BB * CC * LL + (size_t)(b * CC + (o - CC)) * LL + col;
                        *(float2*)(Y + idx) = make_float2(v10, v11);
                    }
                }
            }
        }
    }
#undef STAGE
}

// ---------------- fused GLU + LayerNorm (+ optional act -> bf16), LT=32 ----------------
#define LT 32
#define GLULN_SMEM ((HH * (LT + 1) + 2 * 8 * (LT + 1) + 2 * LT) * 4)

__global__ void k_gluln(const float* __restrict__ t, float* __restrict__ u,
                        __nv_bfloat16* __restrict__ zh, __nv_bfloat16* __restrict__ zl,
                        const float* __restrict__ g, const float* __restrict__ be,
                        int act_mode) {
    extern __shared__ __align__(16) float fsm[];
    float* sv = fsm;
    float* red0 = sv + HH * (LT + 1);
    float* red1 = red0 + 8 * (LT + 1);
    float* smu = red1 + 8 * (LT + 1);
    float* srs = smu + LT;

    int b = blockIdx.y, l0 = blockIdx.x * LT;
    const float* tb = t + (size_t)b * H2 * LL;
    for (int i = threadIdx.x; i < HH * LT; i += 256) {
        int h = i >> 5, l = i & (LT - 1);
        float a = tb[(size_t)h * LL + l0 + l];
        float gg = tb[(size_t)(h + HH) * LL + l0 + l];
        sv[h * (LT + 1) + l] = a * sigf(gg);
    }
    __syncthreads();
    {
        int col = threadIdx.x & (LT - 1);
        int part = threadIdx.x >> 5;
        float s = 0.f, ss = 0.f;
        for (int h = part; h < HH; h += 8) {
            float v = sv[h * (LT + 1) + col];
            s += v;
            ss = fmaf(v, v, ss);
        }
        red0[part * (LT + 1) + col] = s;
        red1[part * (LT + 1) + col] = ss;
        __syncthreads();
        if (part == 0) {
            float S = 0.f, SS = 0.f;
#pragma unroll
            for (int p = 0; p < 8; p++) {
                S += red0[p * (LT + 1) + col];
                SS += red1[p * (LT + 1) + col];
            }
            float mu = S * (1.f / HH);
            float var = SS * (1.f / HH) - mu * mu;
            smu[col] = mu;
            srs[col] = rsqrtf(var + 1e-5f);
        }
        __syncthreads();
    }
    if (!act_mode) {
        float* ub = u + (size_t)b * HH * LL;
        for (int i = threadIdx.x; i < HH * LT; i += 256) {
            int h = i >> 5, l = i & (LT - 1);
            ub[(size_t)h * LL + l0 + l] =
                (sv[h * (LT + 1) + l] - smu[l]) * srs[l] * __ldg(g + h) + __ldg(be + h);
        }
    } else {
        for (int i = threadIdx.x; i < CC * LT; i += 256) {
            int l = i & (LT - 1), h = i >> 5;
            float n0 = (sv[h * (LT + 1) + l] - smu[l]) * srs[l] * __ldg(g + h) + __ldg(be + h);
            float n1 = (sv[(h + CC) * (LT + 1) + l] - smu[l]) * srs[l] * __ldg(g + h + CC) +
                       __ldg(be + h + CC);
            float z = sigf(n0) * tanh_mufu(n1);
            __nv_bfloat16 hh = __float2bfloat16(z);
            size_t idx = (size_t)(b * CC + h) * LL + l0 + l;
            zh[idx] = hh;
            zl[idx] = __float2bfloat16(z - __bfloat162float(hh));
        }
    }
}

// ---------------- launch ----------------
extern "C" void kernel_launch(void* const* d_in, const int* in_sizes, int n_in,
                              void* d_out, int out_size) {
    const float* x    = (const float*)d_in[0];
    const float* demb = (const float*)d_in[1];
    const float* dpW  = (const float*)d_in[2];
    const float* dpb  = (const float*)d_in[3];
    const float* inW  = (const float*)d_in[4];
    const float* inb  = (const float*)d_in[5];
    const float* outW = (const float*)d_in[6];
    const float* outb = (const float*)d_in[7];
    const float* ln1g = (const float*)d_in[8];
    const float* ln1b = (const float*)d_in[9];
    const float* ln2g = (const float*)d_in[10];
    const float* ln2b = (const float*)d_in[11];
    const float* s1_logdt = (const float*)d_in[12];
    const float* s1_Are   = (const float*)d_in[13];
    const float* s1_Aim   = (const float*)d_in[14];
    const float* s1_Cre   = (const float*)d_in[15];
    const float* s1_Cim   = (const float*)d_in[16];
    const float* s1_D     = (const float*)d_in[17];
    const float* s1_oW    = (const float*)d_in[18];
    const float* s1_ob    = (const float*)d_in[19];
    const float* s2_logdt = (const float*)d_in[20];
    const float* s2_Are   = (const float*)d_in[21];
    const float* s2_Aim   = (const float*)d_in[22];
    const float* s2_Cre   = (const float*)d_in[23];
    const float* s2_Cim   = (const float*)d_in[24];
    const float* s2_D     = (const float*)d_in[25];
    const float* s2_oW    = (const float*)d_in[26];
    const float* s2_ob    = (const float*)d_in[27];

    float* out = (float*)d_out;

    float *du, *dt, *de;
    __nv_bfloat16 *bh, *bl, *wh, *wlp;
    cudaGetSymbolAddress((void**)&du, g_u);
    cudaGetSymbolAddress((void**)&dt, g_t);
    cudaGetSymbolAddress((void**)&de, g_e);
    cudaGetSymbolAddress((void**)&bh, g_bh);
    cudaGetSymbolAddress((void**)&bl, g_bl);
    cudaGetSymbolAddress((void**)&wh, g_wh);
    cudaGetSymbolAddress((void**)&wlp, g_wl);

    static int attr_set = 0;
    if (!attr_set) {
        cudaFuncSetAttribute(k_gemm_bf, cudaFuncAttributeMaxDynamicSharedMemorySize, GEMM_SMEM);
        cudaFuncSetAttribute(k_gluln, cudaFuncAttributeMaxDynamicSharedMemorySize, GLULN_SMEM);
        attr_set = 1;
    }

    // 1: all conversions (weights + x)
    k_conv<<<(WTOT / 4 + XTOT / 4) / 256, 256>>>(inW, s1_oW, s2_oW, outW, x, wh, wlp, bh, bl);
    // 2: diffusion bias
    k_debias<<<BB, 256>>>(demb, dpW, dpb, inW, inb, de);
    // 3: in-proj GEMM
    k_gemm_bf<<<dim3(LL / 128, HH / 64, BB), 256, GEMM_SMEM>>>(
        wh + W1_OFF, wlp + W1_OFF, bh, bl, de, 1, du, HH, CC, nullptr, 0);
    // 4: PROFILED — S4 layer 1 SSM
    k_ssm<<<(BB * HH) / 16, 128>>>(du, bh, bl, s1_logdt, s1_Are, s1_Aim, s1_Cre, s1_Cim, s1_D);
    k_gemm_bf<<<dim3(LL / 128, H2 / 64, BB), 256, GEMM_SMEM>>>(
        wh + W2_OFF, wlp + W2_OFF, bh, bl, s1_ob, 0, dt, H2, HH, nullptr, 0);
    k_gluln<<<dim3(LL / LT, BB), 256, GLULN_SMEM>>>(dt, du, nullptr, nullptr, ln1g, ln1b, 0);
    // S4 layer 2
    k_ssm<<<(BB * HH) / 16, 128>>>(du, bh, bl, s2_logdt, s2_Are, s2_Aim, s2_Cre, s2_Cim, s2_D);
    k_gemm_bf<<<dim3(LL / 128, H2 / 64, BB), 256, GEMM_SMEM>>>(
        wh + W3_OFF, wlp + W3_OFF, bh, bl, s2_ob, 0, dt, H2, HH, nullptr, 0);
    // GLU+LN2+act fused -> bf16 gate/filter product
    k_gluln<<<dim3(LL / LT, BB), 256, GLULN_SMEM>>>(dt, nullptr, bh, bl, ln2g, ln2b, 1);
    // out-proj fused with residual/skip split
    k_gemm_bf<<<dim3(LL / 128, HH / 64, BB), 256, GEMM_SMEM>>>(
        wh + W4_OFF, wlp + W4_OFF, bh, bl, outb, 0, out, HH, CC, x, 1);
}